// round 10
// baseline (speedup 1.0000x reference)
#include <cuda_runtime.h>
#include <cstdint>
#include <cstddef>

#define NN 10000
#define NE 160000
#define INVF   0.0279508497187474f    /* 1/sqrt(1280) */
#define RSQRT3 0.5773502691896258f
#define RSQRT2 0.7071067811865476f

// ------------------------- device scratch -------------------------
__device__ int   g_eidx[NE];
__device__ float g_gate[(size_t)NE * 32];
__device__ float g_sn[(size_t)NN * 64];
__device__ float g_vn[(size_t)NN * 96];
__device__ float g_mu[64];
__device__ float g_var[64];
__device__ float g_vnorm[32];
__device__ int   g_flag;
// prepped W fragments, step-PAIR packed:
//   s: [chunk(20)][sp(4)][nt(12)][lane(32)] uint4 = {b(2sp).x, b(2sp).y, b(2sp+1).x, b(2sp+1).y}
//   v: [chunk(20)][sp(4)][nt(4) ][lane(32)] uint4
__device__ uint4 g_ws2[20 * 4 * 12 * 32];
__device__ uint4 g_wv2[20 * 4 * 4 * 32];

// ------------------------- helpers -------------------------
__device__ __forceinline__ uint32_t tf32c(float f) {
    uint32_t u; asm("cvt.rna.tf32.f32 %0, %1;" : "=r"(u) : "f"(f)); return u;
}
__device__ __forceinline__ uint32_t fau(float f) { return __float_as_uint(f); }
__device__ __forceinline__ void mma8(float* d, const uint32_t* a, const uint32_t* b) {
    asm volatile("mma.sync.aligned.m16n8k8.row.col.f32.tf32.tf32.f32 "
        "{%0,%1,%2,%3}, {%4,%5,%6,%7}, {%8,%9}, {%0,%1,%2,%3};"
        : "+f"(d[0]), "+f"(d[1]), "+f"(d[2]), "+f"(d[3])
        : "r"(a[0]), "r"(a[1]), "r"(a[2]), "r"(a[3]), "r"(b[0]), "r"(b[1]));
}
#define BPTR(B, E) ((const uint32_t*)&(B) + 2 * (E))

// ------------------------- small kernels -------------------------
__global__ void detect_kernel(const long long* __restrict__ p) {
    __shared__ int bad;
    if (threadIdx.x == 0) bad = 0;
    __syncthreads();
    long long v = p[threadIdx.x];
    if (v < 0 || v >= NN) bad = 1;
    __syncthreads();
    if (threadIdx.x == 0) g_flag = bad ? 0 : 1;
}

// mega_prep: blocks [0,6250) convert+zero; [6250,6370) s W-prep; [6370,6410) v W-prep
__global__ void mega_prep(const void* __restrict__ src,
                          const float* __restrict__ W_ss, const float* __restrict__ W_vv_s,
                          const float* __restrict__ W_sv, const float* __restrict__ W_vs,
                          const float* __restrict__ W_vv_v) {
    int blk = blockIdx.x;
    if (blk < 6250) {
        int i = blk * 256 + threadIdx.x;
        if (i < NE) {
            int idx;
            if (g_flag) idx = (int)((const long long*)src)[i];
            else        idx = ((const int*)src)[i];
            g_eidx[i] = idx;
        }
        if (i < NN * 64) g_sn[i] = 0.f;
        int j = i - NN * 64;
        if (j >= 0 && j < NN * 96) g_vn[j] = 0.f;
    } else if (blk < 6370) {
        int lin = (blk - 6250) * 256 + threadIdx.x;   // < 30720
        int lane = lin & 31, r = lin >> 5;
        int nt = r % 12, r2 = r / 12;
        int sp = r2 & 3, c = r2 >> 2;
        int k0 = c * 64 + sp * 16 + (lane & 3);
        int n = nt * 8 + (lane >> 2);
        uint4 val;
        {
            int k = k0;
            val.x = tf32c((k < 1024) ? W_ss[(size_t)k * 96 + n] : W_vv_s[(size_t)(k - 1024) * 96 + n]);
            k = k0 + 4;
            val.y = tf32c((k < 1024) ? W_ss[(size_t)k * 96 + n] : W_vv_s[(size_t)(k - 1024) * 96 + n]);
            k = k0 + 8;
            val.z = tf32c((k < 1024) ? W_ss[(size_t)k * 96 + n] : W_vv_s[(size_t)(k - 1024) * 96 + n]);
            k = k0 + 12;
            val.w = tf32c((k < 1024) ? W_ss[(size_t)k * 96 + n] : W_vv_s[(size_t)(k - 1024) * 96 + n]);
        }
        g_ws2[lin] = val;
    } else {
        int lin = (blk - 6370) * 256 + threadIdx.x;   // < 10240
        int lane = lin & 31, r = lin >> 5;
        int nt = r & 3, r2 = r >> 2;
        int sp = r2 & 3, c = r2 >> 2;
        int k0 = c * 64 + sp * 16 + (lane & 3);
        int n = nt * 8 + (lane >> 2);
        uint4 val;
        float f;
        int k = k0;
        f = (k < 512) ? W_sv[(size_t)k * 32 + n] : (k < 1024) ? W_vs[(size_t)(k - 512) * 32 + n] : W_vv_v[(size_t)(k - 1024) * 32 + n];
        val.x = tf32c(f);
        k = k0 + 4;
        f = (k < 512) ? W_sv[(size_t)k * 32 + n] : (k < 1024) ? W_vs[(size_t)(k - 512) * 32 + n] : W_vv_v[(size_t)(k - 1024) * 32 + n];
        val.y = tf32c(f);
        k = k0 + 8;
        f = (k < 512) ? W_sv[(size_t)k * 32 + n] : (k < 1024) ? W_vs[(size_t)(k - 512) * 32 + n] : W_vv_v[(size_t)(k - 1024) * 32 + n];
        val.z = tf32c(f);
        k = k0 + 12;
        f = (k < 512) ? W_sv[(size_t)k * 32 + n] : (k < 1024) ? W_vs[(size_t)(k - 512) * 32 + n] : W_vv_v[(size_t)(k - 1024) * 32 + n];
        val.w = tf32c(f);
        g_wv2[lin] = val;
    }
}

// ------------------------- s-path kernel: 128 edges/CTA -------------------------
__global__ void __launch_bounds__(256, 2) s_kernel(
    const float* __restrict__ x, const float* __restrict__ ea)
{
    const int tx = threadIdx.x, wid = tx >> 5, lane = tx & 31;
    const int g = lane >> 2, t = lane & 3;
    const int wm = wid & 3, wn = wid >> 2;
    const int e_base = blockIdx.x * 128;

    int el[4], node[4];
    const float *px[4], *pa[4];
    el[0] = wm * 16 + g; el[1] = el[0] + 8; el[2] = el[0] + 64; el[3] = el[1] + 64;
#pragma unroll
    for (int r = 0; r < 4; r++) {
        int e = e_base + el[r];
        node[r] = g_eidx[e];
        px[r] = x + (size_t)node[r] * 160;
        pa[r] = ea + (size_t)e * 40;
    }

    // b index: [((c*4+sp)*12 + wn*6 + j)*32 + lane]
    const uint4* wb = g_ws2 + (size_t)(wn * 6) * 32 + lane;

    float acc[2][6][4];
#pragma unroll
    for (int i = 0; i < 2; i++)
#pragma unroll
        for (int j = 0; j < 6; j++)
#pragma unroll
            for (int q = 0; q < 4; q++) acc[i][j][q] = 0.f;

    float eb[4][4];
#pragma unroll
    for (int r = 0; r < 4; r++)
#pragma unroll
        for (int j = 0; j < 4; j++) eb[r][j] = pa[r][t + 4 * j];

    // ---- ss chunks 0..15, x prefetched one chunk ahead
    float4 xn[4];
#pragma unroll
    for (int r = 0; r < 4; r++) xn[r] = *(const float4*)(px[r]);

    for (int c = 0; c < 16; c++) {
        float xa[4][4];
#pragma unroll
        for (int r = 0; r < 4; r++) {
            xa[r][0] = xn[r].x; xa[r][1] = xn[r].y; xa[r][2] = xn[r].z; xa[r][3] = xn[r].w;
        }
        if (c < 15) {
#pragma unroll
            for (int r = 0; r < 4; r++) xn[r] = *(const float4*)(px[r] + (c + 1) * 4);
        }
        const uint4* wc = wb + (size_t)(c * 4) * 12 * 32;
#pragma unroll
        for (int sp = 0; sp < 4; sp++) {
            uint4 b[6];
#pragma unroll
            for (int j = 0; j < 6; j++)
                b[j] = __ldg(wc + (size_t)(sp * 12 + j) * 32);
#pragma unroll
            for (int e2 = 0; e2 < 2; e2++) {
                const int j0 = 2 * e2;
                uint32_t fr[4];
                fr[0] = fau(xa[0][sp] * eb[0][j0]);
                fr[1] = fau(xa[1][sp] * eb[1][j0]);
                fr[2] = fau(xa[0][sp] * eb[0][j0 + 1]);
                fr[3] = fau(xa[1][sp] * eb[1][j0 + 1]);
#pragma unroll
                for (int j = 0; j < 6; j++) mma8(acc[0][j], fr, BPTR(b[j], e2));
                fr[0] = fau(xa[2][sp] * eb[2][j0]);
                fr[1] = fau(xa[3][sp] * eb[3][j0]);
                fr[2] = fau(xa[2][sp] * eb[2][j0 + 1]);
                fr[3] = fau(xa[3][sp] * eb[3][j0 + 1]);
#pragma unroll
                for (int j = 0; j < 6; j++) mma8(acc[1][j], fr, BPTR(b[j], e2));
            }
        }
    }

    // ---- vv chunks 16..19
    float v2[4][2][3];
#pragma unroll
    for (int r = 0; r < 4; r++)
#pragma unroll
        for (int h = 0; h < 2; h++)
#pragma unroll
            for (int m = 0; m < 3; m++) v2[r][h][m] = pa[r][16 + (t + 4 * h) * 3 + m];

    for (int c = 16; c < 20; c++) {
        const uint4* wc = wb + (size_t)(c * 4) * 12 * 32;
        const int vab = (c - 16) * 8;
#pragma unroll
        for (int half = 0; half < 2; half++) {
            const int r0 = half * 2, r1 = r0 + 1;
#pragma unroll
            for (int ks = 0; ks < 2; ks++) {
                float v1b[2][12];
#pragma unroll
                for (int r2 = 0; r2 < 2; r2++) {
                    const float* p = px[r0 + r2] + 64 + (vab + ks * 4) * 3;
                    float4 q0 = ((const float4*)p)[0];
                    float4 q1 = ((const float4*)p)[1];
                    float4 q2 = ((const float4*)p)[2];
                    v1b[r2][0] = q0.x; v1b[r2][1] = q0.y; v1b[r2][2]  = q0.z; v1b[r2][3]  = q0.w;
                    v1b[r2][4] = q1.x; v1b[r2][5] = q1.y; v1b[r2][6]  = q1.z; v1b[r2][7]  = q1.w;
                    v1b[r2][8] = q2.x; v1b[r2][9] = q2.y; v1b[r2][10] = q2.z; v1b[r2][11] = q2.w;
                }
#pragma unroll
                for (int s4p = 0; s4p < 2; s4p++) {
                    const int sp = ks * 2 + s4p;
                    uint4 b[6];
#pragma unroll
                    for (int j = 0; j < 6; j++)
                        b[j] = __ldg(wc + (size_t)(sp * 12 + j) * 32);
#pragma unroll
                    for (int e2 = 0; e2 < 2; e2++) {
                        const int s4 = s4p * 2 + e2;
                        const float* A0 = &v1b[0][s4 * 3];
                        const float* A1 = &v1b[1][s4 * 3];
                        uint32_t fr[4];
                        fr[0] = fau((A0[0]*v2[r0][0][0] + A0[1]*v2[r0][0][1] + A0[2]*v2[r0][0][2]) * RSQRT3);
                        fr[1] = fau((A1[0]*v2[r1][0][0] + A1[1]*v2[r1][0][1] + A1[2]*v2[r1][0][2]) * RSQRT3);
                        fr[2] = fau((A0[0]*v2[r0][1][0] + A0[1]*v2[r0][1][1] + A0[2]*v2[r0][1][2]) * RSQRT3);
                        fr[3] = fau((A1[0]*v2[r1][1][0] + A1[1]*v2[r1][1][1] + A1[2]*v2[r1][1][2]) * RSQRT3);
#pragma unroll
                        for (int j = 0; j < 6; j++) mma8(acc[half][j], fr, BPTR(b[j], e2));
                    }
                }
            }
        }
    }

    // ---- epilogue
#pragma unroll
    for (int i = 0; i < 2; i++) {
#pragma unroll
        for (int j = 0; j < 6; j++) {
            int cb = (wn * 6 + j) * 8 + t * 2;
#pragma unroll
            for (int q = 0; q < 4; q++) {
                int r = i * 2 + ((q >= 2) ? 1 : 0);
                int cch = cb + (q & 1);
                float v = acc[i][j][q] * INVF;
                float sg = 1.f / (1.f + __expf(-v));
                if (cch < 64) atomicAdd(&g_sn[(size_t)node[r] * 64 + cch], v * sg);
                else          g_gate[(size_t)(e_base + el[r]) * 32 + (cch - 64)] = sg;
            }
        }
    }
}

// ------------------------- v-path kernel: 128 edges/CTA -------------------------
__global__ void __launch_bounds__(256, 2) v_kernel(
    const float* __restrict__ x, const float* __restrict__ ea)
{
    const int tx = threadIdx.x, wid = tx >> 5, lane = tx & 31;
    const int g = lane >> 2, t = lane & 3;
    const int wm = wid & 3, wn = wid >> 2;
    const int e_base = blockIdx.x * 128;

    int el[4], node[4];
    const float *px[4], *pa[4];
    el[0] = wm * 16 + g; el[1] = el[0] + 8; el[2] = el[0] + 64; el[3] = el[1] + 64;
#pragma unroll
    for (int r = 0; r < 4; r++) {
        int e = e_base + el[r];
        node[r] = g_eidx[e];
        px[r] = x + (size_t)node[r] * 160;
        pa[r] = ea + (size_t)e * 40;
    }

    // b index: [((c*4+sp)*4 + wn*2 + j)*32 + lane]
    const uint4* wb = g_wv2 + (size_t)(wn * 2) * 32 + lane;

    float acc[2][3][2][4];
#pragma unroll
    for (int i = 0; i < 2; i++)
#pragma unroll
        for (int m = 0; m < 3; m++)
#pragma unroll
            for (int j = 0; j < 2; j++)
#pragma unroll
                for (int q = 0; q < 4; q++) acc[i][m][j][q] = 0.f;

    float v2[4][2][3];
#pragma unroll
    for (int r = 0; r < 4; r++)
#pragma unroll
        for (int h = 0; h < 2; h++)
#pragma unroll
            for (int m = 0; m < 3; m++) v2[r][h][m] = pa[r][16 + (t + 4 * h) * 3 + m];

#define V_MMA_E(B0, B1, E, HALF, FR) do {                                             \
    _Pragma("unroll")                                                                 \
    for (int m = 0; m < 3; m++) {                                                     \
        mma8(acc[HALF][m][0], (FR)[m], BPTR(B0, E));                                  \
        mma8(acc[HALF][m][1], (FR)[m], BPTR(B1, E));                                  \
    }                                                                                 \
} while (0)

    // ---- region A: s1 * v2[m], chunks 0..7
    for (int c = 0; c < 8; c++) {
        const uint4* wc = wb + (size_t)(c * 4) * 4 * 32;
#pragma unroll
        for (int half = 0; half < 2; half++) {
            const int r0 = half * 2, r1 = r0 + 1;
#pragma unroll
            for (int ks = 0; ks < 2; ks++) {
                float s1v[2][4];
#pragma unroll
                for (int r2 = 0; r2 < 2; r2++) {
                    float4 v4 = *(const float4*)(px[r0 + r2] + c * 8 + ks * 4);
                    s1v[r2][0] = v4.x; s1v[r2][1] = v4.y; s1v[r2][2] = v4.z; s1v[r2][3] = v4.w;
                }
#pragma unroll
                for (int s4p = 0; s4p < 2; s4p++) {
                    const int sp = ks * 2 + s4p;
                    uint4 b0 = __ldg(wc + (size_t)(sp * 4 + 0) * 32);
                    uint4 b1 = __ldg(wc + (size_t)(sp * 4 + 1) * 32);
#pragma unroll
                    for (int e2 = 0; e2 < 2; e2++) {
                        const int s4 = s4p * 2 + e2;
                        uint32_t fr[3][4];
#pragma unroll
                        for (int m = 0; m < 3; m++) {
                            fr[m][0] = fau(s1v[0][s4] * v2[r0][0][m]);
                            fr[m][1] = fau(s1v[1][s4] * v2[r1][0][m]);
                            fr[m][2] = fau(s1v[0][s4] * v2[r0][1][m]);
                            fr[m][3] = fau(s1v[1][s4] * v2[r1][1][m]);
                        }
                        V_MMA_E(b0, b1, e2, half, fr);
                    }
                }
            }
        }
    }

    // ---- region B: v1[m] * s2, chunks 8..15
    {
        float s2v[4][4];
#pragma unroll
        for (int r = 0; r < 4; r++)
#pragma unroll
            for (int j = 0; j < 4; j++) s2v[r][j] = pa[r][t + 4 * j];
        for (int c = 8; c < 16; c++) {
            const uint4* wc = wb + (size_t)(c * 4) * 4 * 32;
#pragma unroll
            for (int half = 0; half < 2; half++) {
                const int r0 = half * 2, r1 = r0 + 1;
                float v1b[2][12];
#pragma unroll
                for (int r2 = 0; r2 < 2; r2++) {
                    const float* p = px[r0 + r2] + 64 + (c - 8) * 12;
                    float4 q0 = ((const float4*)p)[0];
                    float4 q1 = ((const float4*)p)[1];
                    float4 q2 = ((const float4*)p)[2];
                    v1b[r2][0] = q0.x; v1b[r2][1] = q0.y; v1b[r2][2]  = q0.z; v1b[r2][3]  = q0.w;
                    v1b[r2][4] = q1.x; v1b[r2][5] = q1.y; v1b[r2][6]  = q1.z; v1b[r2][7]  = q1.w;
                    v1b[r2][8] = q2.x; v1b[r2][9] = q2.y; v1b[r2][10] = q2.z; v1b[r2][11] = q2.w;
                }
#pragma unroll
                for (int sp = 0; sp < 4; sp++) {
                    uint4 b0 = __ldg(wc + (size_t)(sp * 4 + 0) * 32);
                    uint4 b1 = __ldg(wc + (size_t)(sp * 4 + 1) * 32);
#pragma unroll
                    for (int e2 = 0; e2 < 2; e2++) {
                        const int j0 = 2 * e2;
                        uint32_t fr[3][4];
#pragma unroll
                        for (int m = 0; m < 3; m++) {
                            fr[m][0] = fau(v1b[0][sp * 3 + m] * s2v[r0][j0]);
                            fr[m][1] = fau(v1b[1][sp * 3 + m] * s2v[r1][j0]);
                            fr[m][2] = fau(v1b[0][sp * 3 + m] * s2v[r0][j0 + 1]);
                            fr[m][3] = fau(v1b[1][sp * 3 + m] * s2v[r1][j0 + 1]);
                        }
                        V_MMA_E(b0, b1, e2, half, fr);
                    }
                }
            }
        }
    }

    // ---- region C: cross(v1, v2)[m]/sqrt(2), chunks 16..19
    for (int c = 16; c < 20; c++) {
        const uint4* wc = wb + (size_t)(c * 4) * 4 * 32;
        const int vab = (c - 16) * 8;
#pragma unroll
        for (int half = 0; half < 2; half++) {
            const int r0 = half * 2, r1 = r0 + 1;
#pragma unroll
            for (int ks = 0; ks < 2; ks++) {
                float v1b[2][12];
#pragma unroll
                for (int r2 = 0; r2 < 2; r2++) {
                    const float* p = px[r0 + r2] + 64 + (vab + ks * 4) * 3;
                    float4 q0 = ((const float4*)p)[0];
                    float4 q1 = ((const float4*)p)[1];
                    float4 q2 = ((const float4*)p)[2];
                    v1b[r2][0] = q0.x; v1b[r2][1] = q0.y; v1b[r2][2]  = q0.z; v1b[r2][3]  = q0.w;
                    v1b[r2][4] = q1.x; v1b[r2][5] = q1.y; v1b[r2][6]  = q1.z; v1b[r2][7]  = q1.w;
                    v1b[r2][8] = q2.x; v1b[r2][9] = q2.y; v1b[r2][10] = q2.z; v1b[r2][11] = q2.w;
                }
#pragma unroll
                for (int s4p = 0; s4p < 2; s4p++) {
                    const int sp = ks * 2 + s4p;
                    uint4 b0 = __ldg(wc + (size_t)(sp * 4 + 0) * 32);
                    uint4 b1 = __ldg(wc + (size_t)(sp * 4 + 1) * 32);
#pragma unroll
                    for (int e2 = 0; e2 < 2; e2++) {
                        const int s4 = s4p * 2 + e2;
                        const float* A0 = &v1b[0][s4 * 3];
                        const float* A1 = &v1b[1][s4 * 3];
                        uint32_t fr[3][4];
#pragma unroll
                        for (int m = 0; m < 3; m++) {
                            const int m1 = (m == 2) ? 0 : m + 1;
                            const int m2 = (m == 0) ? 2 : m - 1;
                            fr[m][0] = fau((A0[m1] * v2[r0][0][m2] - A0[m2] * v2[r0][0][m1]) * RSQRT2);
                            fr[m][1] = fau((A1[m1] * v2[r1][0][m2] - A1[m2] * v2[r1][0][m1]) * RSQRT2);
                            fr[m][2] = fau((A0[m1] * v2[r0][1][m2] - A0[m2] * v2[r0][1][m1]) * RSQRT2);
                            fr[m][3] = fau((A1[m1] * v2[r1][1][m2] - A1[m2] * v2[r1][1][m1]) * RSQRT2);
                        }
                        V_MMA_E(b0, b1, e2, half, fr);
                    }
                }
            }
        }
    }

    // ---- epilogue: gate & scatter
#pragma unroll
    for (int i = 0; i < 2; i++) {
#pragma unroll
        for (int j = 0; j < 2; j++) {
            int cb = (wn * 2 + j) * 8 + t * 2;
#pragma unroll
            for (int q = 0; q < 4; q++) {
                int r = i * 2 + ((q >= 2) ? 1 : 0);
                int cch = cb + (q & 1);
                float gt = g_gate[(size_t)(e_base + el[r]) * 32 + cch] * INVF;
#pragma unroll
                for (int m = 0; m < 3; m++)
                    atomicAdd(&g_vn[(size_t)node[r] * 96 + cch * 3 + m], acc[i][m][j][q] * gt);
            }
        }
    }
}

// ------------------------- BN stats -------------------------
__global__ void stats_kernel() {
    __shared__ double red[256];
    __shared__ double red2[256];
    int c = blockIdx.x;
    int tx = threadIdx.x;
    double s = 0.0, s2 = 0.0;
    if (c < 64) {
        for (int n = tx; n < NN; n += 256) {
            float v = g_sn[(size_t)n * 64 + c];
            s += (double)v; s2 += (double)v * (double)v;
        }
    } else {
        int cv = c - 64;
        for (int n = tx; n < NN; n += 256) {
            const float* p = &g_vn[(size_t)n * 96 + cv * 3];
            s += (double)p[0] * p[0] + (double)p[1] * p[1] + (double)p[2] * p[2];
        }
    }
    red[tx] = s; red2[tx] = s2;
    __syncthreads();
    for (int o = 128; o > 0; o >>= 1) {
        if (tx < o) { red[tx] += red[tx + o]; red2[tx] += red2[tx + o]; }
        __syncthreads();
    }
    if (tx == 0) {
        if (c < 64) {
            double mu = red[0] / (double)NN;
            g_mu[c] = (float)mu;
            g_var[c] = (float)(red2[0] / (double)NN - mu * mu);
        } else {
            g_vnorm[c - 64] = (float)(red[0] / ((double)NN * 3.0));
        }
    }
}

// ------------------------- finalize -------------------------
__global__ void finalize_kernel(
    const float* __restrict__ x,
    const float* __restrict__ bn_w_s, const float* __restrict__ bn_b_s,
    const float* __restrict__ bn_w_v, float* __restrict__ out)
{
    int idx = blockIdx.x * 256 + threadIdx.x;
    if (idx >= NN * 160) return;
    int n = idx / 160, j = idx % 160;
    float xv = x[idx];
    float r;
    if (j < 64) {
        float v = g_sn[(size_t)n * 64 + j];
        r = (v - g_mu[j]) * rsqrtf(g_var[j] + 1e-5f) * bn_w_s[j] + bn_b_s[j];
    } else {
        int jj = j - 64;
        int a = jj / 3;
        r = g_vn[(size_t)n * 96 + jj] * rsqrtf(g_vnorm[a] + 1e-5f) * bn_w_v[a];
    }
    out[idx] = r + xv;
}

// ------------------------- launcher -------------------------
extern "C" void kernel_launch(void* const* d_in, const int* in_sizes, int n_in,
                              void* d_out, int out_size)
{
    const float* x      = (const float*)d_in[0];
    const float* ea     = (const float*)d_in[1];
    const float* W_ss   = (const float*)d_in[2];
    const float* W_vv_s = (const float*)d_in[3];
    const float* W_sv   = (const float*)d_in[4];
    const float* W_vs   = (const float*)d_in[5];
    const float* W_vv_v = (const float*)d_in[6];
    const float* bnws   = (const float*)d_in[7];
    const float* bnbs   = (const float*)d_in[8];
    const float* bnwv   = (const float*)d_in[9];
    const void*  eidx   = d_in[10];
    float* out = (float*)d_out;

    // launch index 2 == s_kernel, 3 == v_kernel
    detect_kernel<<<1, 256>>>((const long long*)eidx);
    mega_prep<<<6410, 256>>>(eidx, W_ss, W_vv_s, W_sv, W_vs, W_vv_v);
    s_kernel<<<NE / 128, 256>>>(x, ea);
    v_kernel<<<NE / 128, 256>>>(x, ea);
    stats_kernel<<<96, 256>>>();
    finalize_kernel<<<(NN * 160 + 255) / 256, 256>>>(x, bnws, bnbs, bnwv, out);
}

// round 11
// speedup vs baseline: 1.3996x; 1.3996x over previous
#include <cuda_runtime.h>
#include <cstdint>
#include <cstddef>

#define NN 10000
#define NE 160000
#define INVF   0.0279508497187474f    /* 1/sqrt(1280) */
#define RSQRT3 0.5773502691896258f
#define RSQRT2 0.7071067811865476f

// ------------------------- device scratch -------------------------
__device__ int   g_eidx[NE];
__device__ float g_gate[(size_t)NE * 32];
__device__ float g_sn[(size_t)NN * 64];
__device__ float g_vn[(size_t)NN * 96];
__device__ float g_mu[64];
__device__ float g_var[64];
__device__ float g_vnorm[32];
__device__ int   g_flag;
// prepped W fragments: [chunk][step(8)][nt][lane(32)][2] tf32
__device__ uint32_t g_ws[20 * 6144];   // nt = 12  (s-path, N=96)
__device__ uint32_t g_wv[20 * 2048];   // nt = 4   (v-path, N=32)

// ------------------------- helpers -------------------------
__device__ __forceinline__ uint32_t tf32c(float f) {
    uint32_t u; asm("cvt.rna.tf32.f32 %0, %1;" : "=r"(u) : "f"(f)); return u;
}
__device__ __forceinline__ uint32_t fau(float f) { return __float_as_uint(f); }
__device__ __forceinline__ void mma8(float* d, const uint32_t* a, const uint32_t* b) {
    asm volatile("mma.sync.aligned.m16n8k8.row.col.f32.tf32.tf32.f32 "
        "{%0,%1,%2,%3}, {%4,%5,%6,%7}, {%8,%9}, {%0,%1,%2,%3};"
        : "+f"(d[0]), "+f"(d[1]), "+f"(d[2]), "+f"(d[3])
        : "r"(a[0]), "r"(a[1]), "r"(a[2]), "r"(a[3]), "r"(b[0]), "r"(b[1]));
}
__device__ __forceinline__ uint32_t smem_u32(const void* p) {
    uint32_t a;
    asm("{ .reg .u64 t; cvta.to.shared.u64 t, %1; cvt.u32.u64 %0, t; }" : "=r"(a) : "l"(p));
    return a;
}
__device__ __forceinline__ void cp16(uint32_t dst, const void* src) {
    asm volatile("cp.async.cg.shared.global [%0], [%1], 16;" :: "r"(dst), "l"(src) : "memory");
}
#define CP_COMMIT() asm volatile("cp.async.commit_group;" ::: "memory")
#define CP_WAIT0()  asm volatile("cp.async.wait_group 0;" ::: "memory")

// ------------------------- small kernels -------------------------
__global__ void detect_kernel(const long long* __restrict__ p) {
    __shared__ int bad;
    if (threadIdx.x == 0) bad = 0;
    __syncthreads();
    long long v = p[threadIdx.x];
    if (v < 0 || v >= NN) bad = 1;
    __syncthreads();
    if (threadIdx.x == 0) g_flag = bad ? 0 : 1;
}

// mega_prep: blocks [0,6250) convert+zero; [6250,6490) w_prep_s; [6490,6570) w_prep_v
__global__ void mega_prep(const void* __restrict__ src,
                          const float* __restrict__ W_ss, const float* __restrict__ W_vv_s,
                          const float* __restrict__ W_sv, const float* __restrict__ W_vs,
                          const float* __restrict__ W_vv_v) {
    int blk = blockIdx.x;
    if (blk < 6250) {
        int i = blk * 256 + threadIdx.x;
        if (i < NE) {
            int idx;
            if (g_flag) idx = (int)((const long long*)src)[i];
            else        idx = ((const int*)src)[i];
            g_eidx[i] = idx;
        }
        if (i < NN * 64) g_sn[i] = 0.f;
        int j = i - NN * 64;
        if (j >= 0 && j < NN * 96) g_vn[j] = 0.f;
    } else if (blk < 6490) {
        int lin = (blk - 6250) * 256 + threadIdx.x;
        if (lin >= 61440) return;
        int lane = lin & 31, r = lin >> 5;
        int nt = r % 12; r /= 12;
        int k = (r >> 3) * 64 + (r & 7) * 8 + (lane & 3);
        int n = nt * 8 + (lane >> 2);
        float f0 = (k < 1024) ? W_ss[(size_t)k * 96 + n] : W_vv_s[(size_t)(k - 1024) * 96 + n];
        float f1 = (k < 1024) ? W_ss[(size_t)(k + 4) * 96 + n] : W_vv_s[(size_t)(k - 1020) * 96 + n];
        g_ws[lin * 2] = tf32c(f0); g_ws[lin * 2 + 1] = tf32c(f1);
    } else {
        int lin = (blk - 6490) * 256 + threadIdx.x;
        if (lin >= 20480) return;
        int lane = lin & 31, r = lin >> 5;
        int nt = r & 3; r >>= 2;
        int k = (r >> 3) * 64 + (r & 7) * 8 + (lane & 3);
        int n = nt * 8 + (lane >> 2);
        float f0, f1;
        if (k < 512)       { f0 = W_sv[(size_t)k * 32 + n];          f1 = W_sv[(size_t)(k + 4) * 32 + n]; }
        else if (k < 1024) { f0 = W_vs[(size_t)(k - 512) * 32 + n];  f1 = W_vs[(size_t)(k - 508) * 32 + n]; }
        else               { f0 = W_vv_v[(size_t)(k - 1024) * 32 + n]; f1 = W_vv_v[(size_t)(k - 1020) * 32 + n]; }
        g_wv[lin * 2] = tf32c(f0); g_wv[lin * 2 + 1] = tf32c(f1);
    }
}

// ------------------------- s-path kernel: 128 edges/CTA, smem W pipeline (R7 best) -------------------------
#define S_WCH 6144
__global__ void __launch_bounds__(256, 2) s_kernel(
    const float* __restrict__ x, const float* __restrict__ ea)
{
    __shared__ uint32_t SW[2][S_WCH];
    const int tx = threadIdx.x, wid = tx >> 5, lane = tx & 31;
    const int g = lane >> 2, t = lane & 3;
    const int wm = wid & 3, wn = wid >> 2;
    const int e_base = blockIdx.x * 128;

    int el[4], node[4];
    const float *px[4], *pa[4];
    el[0] = wm * 16 + g; el[1] = el[0] + 8; el[2] = el[0] + 64; el[3] = el[1] + 64;
#pragma unroll
    for (int r = 0; r < 4; r++) {
        int e = e_base + el[r];
        node[r] = g_eidx[e];
        px[r] = x + (size_t)node[r] * 160;
        pa[r] = ea + (size_t)e * 40;
    }

    const uint32_t swb = smem_u32(SW);
    {
#pragma unroll
        for (int it = 0; it < 6; it++)
            cp16(swb + (uint32_t)(tx + it * 256) * 16, (const char*)g_ws + (tx + it * 256) * 16);
        CP_COMMIT(); CP_WAIT0();
        __syncthreads();
    }

    float acc[2][6][4];
#pragma unroll
    for (int i = 0; i < 2; i++)
#pragma unroll
        for (int j = 0; j < 6; j++)
#pragma unroll
            for (int q = 0; q < 4; q++) acc[i][j][q] = 0.f;

    float eb[4][4];
#pragma unroll
    for (int r = 0; r < 4; r++)
#pragma unroll
        for (int j = 0; j < 4; j++) eb[r][j] = pa[r][t + 4 * j];

    // ---- ss chunks 0..15
    for (int c = 0; c < 16; c++) {
        const int buf = c & 1;
        {
            const char* src = (const char*)(g_ws + (size_t)(c + 1) * S_WCH);
            uint32_t dst = swb + (buf ^ 1) * (S_WCH * 4);
#pragma unroll
            for (int it = 0; it < 6; it++)
                cp16(dst + (uint32_t)(tx + it * 256) * 16, src + (tx + it * 256) * 16);
            CP_COMMIT();
        }
        float xa[4][4];
#pragma unroll
        for (int r = 0; r < 4; r++) {
            float4 v4 = *(const float4*)(px[r] + c * 4);
            xa[r][0] = v4.x; xa[r][1] = v4.y; xa[r][2] = v4.z; xa[r][3] = v4.w;
        }
        const uint32_t* cw = SW[buf];
#pragma unroll
        for (int s = 0; s < 8; s++) {
            const int ai = s >> 1, j0 = 2 * (s & 1);
            uint2 b[6];
#pragma unroll
            for (int j = 0; j < 6; j++)
                b[j] = *(const uint2*)(cw + (size_t)((s * 12 + wn * 6 + j) * 32 + lane) * 2);
            uint32_t fr[4];
            fr[0] = fau(xa[0][ai] * eb[0][j0]);
            fr[1] = fau(xa[1][ai] * eb[1][j0]);
            fr[2] = fau(xa[0][ai] * eb[0][j0 + 1]);
            fr[3] = fau(xa[1][ai] * eb[1][j0 + 1]);
#pragma unroll
            for (int j = 0; j < 6; j++) mma8(acc[0][j], fr, (const uint32_t*)&b[j]);
            fr[0] = fau(xa[2][ai] * eb[2][j0]);
            fr[1] = fau(xa[3][ai] * eb[3][j0]);
            fr[2] = fau(xa[2][ai] * eb[2][j0 + 1]);
            fr[3] = fau(xa[3][ai] * eb[3][j0 + 1]);
#pragma unroll
            for (int j = 0; j < 6; j++) mma8(acc[1][j], fr, (const uint32_t*)&b[j]);
        }
        CP_WAIT0();
        __syncthreads();
    }

    // ---- vv chunks 16..19
    float v2[4][2][3];
#pragma unroll
    for (int r = 0; r < 4; r++)
#pragma unroll
        for (int h = 0; h < 2; h++)
#pragma unroll
            for (int m = 0; m < 3; m++) v2[r][h][m] = pa[r][16 + (t + 4 * h) * 3 + m];

    for (int c = 16; c < 20; c++) {
        const int buf = c & 1;
        if (c < 19) {
            const char* src = (const char*)(g_ws + (size_t)(c + 1) * S_WCH);
            uint32_t dst = swb + (buf ^ 1) * (S_WCH * 4);
#pragma unroll
            for (int it = 0; it < 6; it++)
                cp16(dst + (uint32_t)(tx + it * 256) * 16, src + (tx + it * 256) * 16);
            CP_COMMIT();
        }
        const uint32_t* cw = SW[buf];
        const int vab = (c - 16) * 8;
#pragma unroll
        for (int half = 0; half < 2; half++) {
            const int r0 = half * 2, r1 = r0 + 1;
#pragma unroll
            for (int ks = 0; ks < 2; ks++) {
                float v1b[2][12];
#pragma unroll
                for (int r2 = 0; r2 < 2; r2++) {
                    const float* p = px[r0 + r2] + 64 + (vab + ks * 4) * 3;
                    float4 q0 = ((const float4*)p)[0];
                    float4 q1 = ((const float4*)p)[1];
                    float4 q2 = ((const float4*)p)[2];
                    v1b[r2][0] = q0.x; v1b[r2][1] = q0.y; v1b[r2][2]  = q0.z; v1b[r2][3]  = q0.w;
                    v1b[r2][4] = q1.x; v1b[r2][5] = q1.y; v1b[r2][6]  = q1.z; v1b[r2][7]  = q1.w;
                    v1b[r2][8] = q2.x; v1b[r2][9] = q2.y; v1b[r2][10] = q2.z; v1b[r2][11] = q2.w;
                }
#pragma unroll
                for (int s4 = 0; s4 < 4; s4++) {
                    const int s = ks * 4 + s4;
                    uint2 b[6];
#pragma unroll
                    for (int j = 0; j < 6; j++)
                        b[j] = *(const uint2*)(cw + (size_t)((s * 12 + wn * 6 + j) * 32 + lane) * 2);
                    const float* A0 = &v1b[0][s4 * 3];
                    const float* A1 = &v1b[1][s4 * 3];
                    uint32_t fr[4];
                    fr[0] = fau((A0[0]*v2[r0][0][0] + A0[1]*v2[r0][0][1] + A0[2]*v2[r0][0][2]) * RSQRT3);
                    fr[1] = fau((A1[0]*v2[r1][0][0] + A1[1]*v2[r1][0][1] + A1[2]*v2[r1][0][2]) * RSQRT3);
                    fr[2] = fau((A0[0]*v2[r0][1][0] + A0[1]*v2[r0][1][1] + A0[2]*v2[r0][1][2]) * RSQRT3);
                    fr[3] = fau((A1[0]*v2[r1][1][0] + A1[1]*v2[r1][1][1] + A1[2]*v2[r1][1][2]) * RSQRT3);
#pragma unroll
                    for (int j = 0; j < 6; j++) mma8(acc[half][j], fr, (const uint32_t*)&b[j]);
                }
            }
        }
        if (c < 19) CP_WAIT0();
        __syncthreads();
    }

    // ---- epilogue
#pragma unroll
    for (int i = 0; i < 2; i++) {
#pragma unroll
        for (int j = 0; j < 6; j++) {
            int cb = (wn * 6 + j) * 8 + t * 2;
#pragma unroll
            for (int q = 0; q < 4; q++) {
                int r = i * 2 + ((q >= 2) ? 1 : 0);
                int cch = cb + (q & 1);
                float v = acc[i][j][q] * INVF;
                float sg = 1.f / (1.f + __expf(-v));
                if (cch < 64) atomicAdd(&g_sn[(size_t)node[r] * 64 + cch], v * sg);
                else          g_gate[(size_t)(e_base + el[r]) * 32 + (cch - 64)] = sg;
            }
        }
    }
}

// ------------------------- v-path kernel: 128 edges/CTA, no smem, W via LDG (R9 best) -------------------------
__global__ void __launch_bounds__(256, 2) v_kernel(
    const float* __restrict__ x, const float* __restrict__ ea)
{
    const int tx = threadIdx.x, wid = tx >> 5, lane = tx & 31;
    const int g = lane >> 2, t = lane & 3;
    const int wm = wid & 3, wn = wid >> 2;
    const int e_base = blockIdx.x * 128;

    int el[4], node[4];
    const float *px[4], *pa[4];
    el[0] = wm * 16 + g; el[1] = el[0] + 8; el[2] = el[0] + 64; el[3] = el[1] + 64;
#pragma unroll
    for (int r = 0; r < 4; r++) {
        int e = e_base + el[r];
        node[r] = g_eidx[e];
        px[r] = x + (size_t)node[r] * 160;
        pa[r] = ea + (size_t)e * 40;
    }

    const uint2* wb = (const uint2*)g_wv + (size_t)(wn * 2) * 32 + lane;

    float acc[2][3][2][4];
#pragma unroll
    for (int i = 0; i < 2; i++)
#pragma unroll
        for (int m = 0; m < 3; m++)
#pragma unroll
            for (int j = 0; j < 2; j++)
#pragma unroll
                for (int q = 0; q < 4; q++) acc[i][m][j][q] = 0.f;

    float v2[4][2][3];
#pragma unroll
    for (int r = 0; r < 4; r++)
#pragma unroll
        for (int h = 0; h < 2; h++)
#pragma unroll
            for (int m = 0; m < 3; m++) v2[r][h][m] = pa[r][16 + (t + 4 * h) * 3 + m];

#define V_MMA_H(WC, S, HALF, FR) do {                                                 \
    uint2 b0 = __ldg((WC) + (size_t)((S) * 4 + 0) * 32);                              \
    uint2 b1 = __ldg((WC) + (size_t)((S) * 4 + 1) * 32);                              \
    _Pragma("unroll")                                                                 \
    for (int m = 0; m < 3; m++) {                                                     \
        mma8(acc[HALF][m][0], (FR)[m], (const uint32_t*)&b0);                         \
        mma8(acc[HALF][m][1], (FR)[m], (const uint32_t*)&b1);                         \
    }                                                                                 \
} while (0)

    // ---- region A: s1 * v2[m], chunks 0..7
    for (int c = 0; c < 8; c++) {
        const uint2* wc = wb + (size_t)(c * 8) * 4 * 32;
#pragma unroll
        for (int half = 0; half < 2; half++) {
            const int r0 = half * 2, r1 = r0 + 1;
#pragma unroll
            for (int ks = 0; ks < 2; ks++) {
                float s1v[2][4];
#pragma unroll
                for (int r2 = 0; r2 < 2; r2++) {
                    float4 v4 = *(const float4*)(px[r0 + r2] + c * 8 + ks * 4);
                    s1v[r2][0] = v4.x; s1v[r2][1] = v4.y; s1v[r2][2] = v4.z; s1v[r2][3] = v4.w;
                }
#pragma unroll
                for (int s4 = 0; s4 < 4; s4++) {
                    const int s = ks * 4 + s4;
                    uint32_t fr[3][4];
#pragma unroll
                    for (int m = 0; m < 3; m++) {
                        fr[m][0] = fau(s1v[0][s4] * v2[r0][0][m]);
                        fr[m][1] = fau(s1v[1][s4] * v2[r1][0][m]);
                        fr[m][2] = fau(s1v[0][s4] * v2[r0][1][m]);
                        fr[m][3] = fau(s1v[1][s4] * v2[r1][1][m]);
                    }
                    V_MMA_H(wc, s, half, fr);
                }
            }
        }
    }

    // ---- region B: v1[m] * s2, chunks 8..15
    {
        float s2v[4][4];
#pragma unroll
        for (int r = 0; r < 4; r++)
#pragma unroll
            for (int j = 0; j < 4; j++) s2v[r][j] = pa[r][t + 4 * j];
        for (int c = 8; c < 16; c++) {
            const uint2* wc = wb + (size_t)(c * 8) * 4 * 32;
#pragma unroll
            for (int half = 0; half < 2; half++) {
                const int r0 = half * 2, r1 = r0 + 1;
                float v1b[2][12];
#pragma unroll
                for (int r2 = 0; r2 < 2; r2++) {
                    const float* p = px[r0 + r2] + 64 + (c - 8) * 12;
                    float4 q0 = ((const float4*)p)[0];
                    float4 q1 = ((const float4*)p)[1];
                    float4 q2 = ((const float4*)p)[2];
                    v1b[r2][0] = q0.x; v1b[r2][1] = q0.y; v1b[r2][2]  = q0.z; v1b[r2][3]  = q0.w;
                    v1b[r2][4] = q1.x; v1b[r2][5] = q1.y; v1b[r2][6]  = q1.z; v1b[r2][7]  = q1.w;
                    v1b[r2][8] = q2.x; v1b[r2][9] = q2.y; v1b[r2][10] = q2.z; v1b[r2][11] = q2.w;
                }
#pragma unroll
                for (int s = 0; s < 8; s++) {
                    const int va = s >> 1, j0 = 2 * (s & 1);
                    uint32_t fr[3][4];
#pragma unroll
                    for (int m = 0; m < 3; m++) {
                        fr[m][0] = fau(v1b[0][va * 3 + m] * s2v[r0][j0]);
                        fr[m][1] = fau(v1b[1][va * 3 + m] * s2v[r1][j0]);
                        fr[m][2] = fau(v1b[0][va * 3 + m] * s2v[r0][j0 + 1]);
                        fr[m][3] = fau(v1b[1][va * 3 + m] * s2v[r1][j0 + 1]);
                    }
                    V_MMA_H(wc, s, half, fr);
                }
            }
        }
    }

    // ---- region C: cross(v1, v2)[m]/sqrt(2), chunks 16..19
    for (int c = 16; c < 20; c++) {
        const uint2* wc = wb + (size_t)(c * 8) * 4 * 32;
        const int vab = (c - 16) * 8;
#pragma unroll
        for (int half = 0; half < 2; half++) {
            const int r0 = half * 2, r1 = r0 + 1;
#pragma unroll
            for (int ks = 0; ks < 2; ks++) {
                float v1b[2][12];
#pragma unroll
                for (int r2 = 0; r2 < 2; r2++) {
                    const float* p = px[r0 + r2] + 64 + (vab + ks * 4) * 3;
                    float4 q0 = ((const float4*)p)[0];
                    float4 q1 = ((const float4*)p)[1];
                    float4 q2 = ((const float4*)p)[2];
                    v1b[r2][0] = q0.x; v1b[r2][1] = q0.y; v1b[r2][2]  = q0.z; v1b[r2][3]  = q0.w;
                    v1b[r2][4] = q1.x; v1b[r2][5] = q1.y; v1b[r2][6]  = q1.z; v1b[r2][7]  = q1.w;
                    v1b[r2][8] = q2.x; v1b[r2][9] = q2.y; v1b[r2][10] = q2.z; v1b[r2][11] = q2.w;
                }
#pragma unroll
                for (int s4 = 0; s4 < 4; s4++) {
                    const int s = ks * 4 + s4;
                    const float* A0 = &v1b[0][s4 * 3];
                    const float* A1 = &v1b[1][s4 * 3];
                    uint32_t fr[3][4];
#pragma unroll
                    for (int m = 0; m < 3; m++) {
                        const int m1 = (m == 2) ? 0 : m + 1;
                        const int m2 = (m == 0) ? 2 : m - 1;
                        fr[m][0] = fau((A0[m1] * v2[r0][0][m2] - A0[m2] * v2[r0][0][m1]) * RSQRT2);
                        fr[m][1] = fau((A1[m1] * v2[r1][0][m2] - A1[m2] * v2[r1][0][m1]) * RSQRT2);
                        fr[m][2] = fau((A0[m1] * v2[r0][1][m2] - A0[m2] * v2[r0][1][m1]) * RSQRT2);
                        fr[m][3] = fau((A1[m1] * v2[r1][1][m2] - A1[m2] * v2[r1][1][m1]) * RSQRT2);
                    }
                    V_MMA_H(wc, s, half, fr);
                }
            }
        }
    }

    // ---- epilogue: gate & scatter
#pragma unroll
    for (int i = 0; i < 2; i++) {
#pragma unroll
        for (int j = 0; j < 2; j++) {
            int cb = (wn * 2 + j) * 8 + t * 2;
#pragma unroll
            for (int q = 0; q < 4; q++) {
                int r = i * 2 + ((q >= 2) ? 1 : 0);
                int cch = cb + (q & 1);
                float gt = g_gate[(size_t)(e_base + el[r]) * 32 + cch] * INVF;
#pragma unroll
                for (int m = 0; m < 3; m++)
                    atomicAdd(&g_vn[(size_t)node[r] * 96 + cch * 3 + m], acc[i][m][j][q] * gt);
            }
        }
    }
}

// ------------------------- BN stats -------------------------
__global__ void stats_kernel() {
    __shared__ double red[256];
    __shared__ double red2[256];
    int c = blockIdx.x;
    int tx = threadIdx.x;
    double s = 0.0, s2 = 0.0;
    if (c < 64) {
        for (int n = tx; n < NN; n += 256) {
            float v = g_sn[(size_t)n * 64 + c];
            s += (double)v; s2 += (double)v * (double)v;
        }
    } else {
        int cv = c - 64;
        for (int n = tx; n < NN; n += 256) {
            const float* p = &g_vn[(size_t)n * 96 + cv * 3];
            s += (double)p[0] * p[0] + (double)p[1] * p[1] + (double)p[2] * p[2];
        }
    }
    red[tx] = s; red2[tx] = s2;
    __syncthreads();
    for (int o = 128; o > 0; o >>= 1) {
        if (tx < o) { red[tx] += red[tx + o]; red2[tx] += red2[tx + o]; }
        __syncthreads();
    }
    if (tx == 0) {
        if (c < 64) {
            double mu = red[0] / (double)NN;
            g_mu[c] = (float)mu;
            g_var[c] = (float)(red2[0] / (double)NN - mu * mu);
        } else {
            g_vnorm[c - 64] = (float)(red[0] / ((double)NN * 3.0));
        }
    }
}

// ------------------------- finalize -------------------------
__global__ void finalize_kernel(
    const float* __restrict__ x,
    const float* __restrict__ bn_w_s, const float* __restrict__ bn_b_s,
    const float* __restrict__ bn_w_v, float* __restrict__ out)
{
    int idx = blockIdx.x * 256 + threadIdx.x;
    if (idx >= NN * 160) return;
    int n = idx / 160, j = idx % 160;
    float xv = x[idx];
    float r;
    if (j < 64) {
        float v = g_sn[(size_t)n * 64 + j];
        r = (v - g_mu[j]) * rsqrtf(g_var[j] + 1e-5f) * bn_w_s[j] + bn_b_s[j];
    } else {
        int jj = j - 64;
        int a = jj / 3;
        r = g_vn[(size_t)n * 96 + jj] * rsqrtf(g_vnorm[a] + 1e-5f) * bn_w_v[a];
    }
    out[idx] = r + xv;
}

// ------------------------- launcher -------------------------
extern "C" void kernel_launch(void* const* d_in, const int* in_sizes, int n_in,
                              void* d_out, int out_size)
{
    const float* x      = (const float*)d_in[0];
    const float* ea     = (const float*)d_in[1];
    const float* W_ss   = (const float*)d_in[2];
    const float* W_vv_s = (const float*)d_in[3];
    const float* W_sv   = (const float*)d_in[4];
    const float* W_vs   = (const float*)d_in[5];
    const float* W_vv_v = (const float*)d_in[6];
    const float* bnws   = (const float*)d_in[7];
    const float* bnbs   = (const float*)d_in[8];
    const float* bnwv   = (const float*)d_in[9];
    const void*  eidx   = d_in[10];
    float* out = (float*)d_out;

    // launch index 2 == s_kernel, 3 == v_kernel
    detect_kernel<<<1, 256>>>((const long long*)eidx);
    mega_prep<<<6570, 256>>>(eidx, W_ss, W_vv_s, W_sv, W_vs, W_vv_v);
    s_kernel<<<NE / 128, 256>>>(x, ea);
    v_kernel<<<NE / 128, 256>>>(x, ea);
    stats_kernel<<<96, 256>>>();
    finalize_kernel<<<(NN * 160 + 255) / 256, 256>>>(x, bnws, bnbs, bnwv, out);
}

// round 12
// speedup vs baseline: 1.8428x; 1.3167x over previous
#include <cuda_runtime.h>
#include <cstdint>
#include <cstddef>

#define NN 10000
#define NE 160000
#define INVF   0.0279508497187474f    /* 1/sqrt(1280) */
#define RSQRT3 0.5773502691896258f
#define RSQRT2 0.7071067811865476f

// ------------------------- device scratch -------------------------
__device__ int   g_eidx[NE];
__device__ float g_gate[(size_t)NE * 32];
__device__ float g_sn[(size_t)NN * 64];
__device__ float g_vn[(size_t)NN * 96];
__device__ float g_mu[64];
__device__ float g_var[64];
__device__ float g_vnorm[32];
__device__ int   g_flag;
// fp16 W fragments (m16n8k16): [chunk(20)][step(4)][nt][lane(32)] uint2
//   uint2.x = pack(k0+2t, k0+2t+1), uint2.y = pack(k0+2t+8, k0+2t+9), col = nt*8 + lane/4
__device__ uint2 g_wsh[20 * 4 * 12 * 32];   // s-path, N=96
__device__ uint2 g_wvh[20 * 4 * 4 * 32];    // v-path, N=32

// ------------------------- helpers -------------------------
__device__ __forceinline__ uint32_t h2(float hi, float lo) {
    uint32_t r; asm("cvt.rn.f16x2.f32 %0, %1, %2;" : "=r"(r) : "f"(hi), "f"(lo)); return r;
}
__device__ __forceinline__ void mma16(float* d, const uint32_t* a, const uint32_t* b) {
    asm volatile("mma.sync.aligned.m16n8k16.row.col.f32.f16.f16.f32 "
        "{%0,%1,%2,%3}, {%4,%5,%6,%7}, {%8,%9}, {%0,%1,%2,%3};"
        : "+f"(d[0]), "+f"(d[1]), "+f"(d[2]), "+f"(d[3])
        : "r"(a[0]), "r"(a[1]), "r"(a[2]), "r"(a[3]), "r"(b[0]), "r"(b[1]));
}
__device__ __forceinline__ uint32_t smem_u32(const void* p) {
    uint32_t a;
    asm("{ .reg .u64 t; cvta.to.shared.u64 t, %1; cvt.u32.u64 %0, t; }" : "=r"(a) : "l"(p));
    return a;
}
__device__ __forceinline__ void cp16(uint32_t dst, const void* src) {
    asm volatile("cp.async.cg.shared.global [%0], [%1], 16;" :: "r"(dst), "l"(src) : "memory");
}
#define CP_COMMIT() asm volatile("cp.async.commit_group;" ::: "memory")
#define CP_WAIT0()  asm volatile("cp.async.wait_group 0;" ::: "memory")

// ------------------------- small kernels -------------------------
__global__ void detect_kernel(const long long* __restrict__ p) {
    __shared__ int bad;
    if (threadIdx.x == 0) bad = 0;
    __syncthreads();
    long long v = p[threadIdx.x];
    if (v < 0 || v >= NN) bad = 1;
    __syncthreads();
    if (threadIdx.x == 0) g_flag = bad ? 0 : 1;
}

// mega_prep: [0,6250) convert+zero; [6250,6370) s W-prep; [6370,6410) v W-prep
__global__ void mega_prep(const void* __restrict__ src,
                          const float* __restrict__ W_ss, const float* __restrict__ W_vv_s,
                          const float* __restrict__ W_sv, const float* __restrict__ W_vs,
                          const float* __restrict__ W_vv_v) {
    int blk = blockIdx.x;
    if (blk < 6250) {
        int i = blk * 256 + threadIdx.x;
        if (i < NE) {
            int idx;
            if (g_flag) idx = (int)((const long long*)src)[i];
            else        idx = ((const int*)src)[i];
            g_eidx[i] = idx;
        }
        if (i < NN * 64) g_sn[i] = 0.f;
        int j = i - NN * 64;
        if (j >= 0 && j < NN * 96) g_vn[j] = 0.f;
    } else if (blk < 6370) {
        int lin = (blk - 6250) * 256 + threadIdx.x;    // < 30720
        int lane = lin & 31, r = lin >> 5;
        int nt = r % 12, r2 = r / 12;
        int s = r2 & 3, c = r2 >> 2;
        int k0 = c * 64 + s * 16 + 2 * (lane & 3);
        int n = nt * 8 + (lane >> 2);
#define WS(K) (((K) < 1024) ? W_ss[(size_t)(K) * 96 + n] : W_vv_s[(size_t)((K) - 1024) * 96 + n])
        uint2 val;
        val.x = h2(WS(k0 + 1), WS(k0));
        val.y = h2(WS(k0 + 9), WS(k0 + 8));
#undef WS
        g_wsh[lin] = val;
    } else {
        int lin = (blk - 6370) * 256 + threadIdx.x;    // < 10240
        int lane = lin & 31, r = lin >> 5;
        int nt = r & 3, r2 = r >> 2;
        int s = r2 & 3, c = r2 >> 2;
        int k0 = c * 64 + s * 16 + 2 * (lane & 3);
        int n = nt * 8 + (lane >> 2);
#define WV(K) (((K) < 512) ? W_sv[(size_t)(K) * 32 + n] : ((K) < 1024) ? W_vs[(size_t)((K) - 512) * 32 + n] : W_vv_v[(size_t)((K) - 1024) * 32 + n])
        uint2 val;
        val.x = h2(WV(k0 + 1), WV(k0));
        val.y = h2(WV(k0 + 9), WV(k0 + 8));
#undef WV
        g_wvh[lin] = val;
    }
}

// ------------------------- s-path kernel: 128 edges/CTA, fp16 mma, smem W pipeline -------------------------
#define S_WCH 1536   /* uint2 per chunk = 4 steps * 12 nt * 32 lanes */
__global__ void __launch_bounds__(256, 2) s_kernel(
    const float* __restrict__ x, const float* __restrict__ ea)
{
    __shared__ uint2 SW[2][S_WCH];
    const int tx = threadIdx.x, wid = tx >> 5, lane = tx & 31;
    const int g = lane >> 2, t = lane & 3;
    const int wm = wid & 3, wn = wid >> 2;
    const int e_base = blockIdx.x * 128;

    int el[4], node[4];
    const float *px[4], *pa[4];
    el[0] = wm * 16 + g; el[1] = el[0] + 8; el[2] = el[0] + 64; el[3] = el[1] + 64;
#pragma unroll
    for (int r = 0; r < 4; r++) {
        int e = e_base + el[r];
        node[r] = g_eidx[e];
        px[r] = x + (size_t)node[r] * 160;
        pa[r] = ea + (size_t)e * 40;
    }

    const uint32_t swb = smem_u32(SW);
    {
#pragma unroll
        for (int it = 0; it < 3; it++)
            cp16(swb + (uint32_t)(tx + it * 256) * 16, (const char*)g_wsh + (tx + it * 256) * 16);
        CP_COMMIT(); CP_WAIT0();
        __syncthreads();
    }

    float acc[2][6][4];
#pragma unroll
    for (int i = 0; i < 2; i++)
#pragma unroll
        for (int j = 0; j < 6; j++)
#pragma unroll
            for (int q = 0; q < 4; q++) acc[i][j][q] = 0.f;

    // eb2[r] = {ea[2t], ea[2t+1], ea[2t+8], ea[2t+9]}
    float eb2[4][4];
#pragma unroll
    for (int r = 0; r < 4; r++) {
        eb2[r][0] = pa[r][2 * t];     eb2[r][1] = pa[r][2 * t + 1];
        eb2[r][2] = pa[r][2 * t + 8]; eb2[r][3] = pa[r][2 * t + 9];
    }

    // ---- ss chunks 0..15 (step s uses x[e][c*4+s], all 16 ea scalars)
    for (int c = 0; c < 16; c++) {
        const int buf = c & 1;
        {
            const char* src = (const char*)(g_wsh + (size_t)(c + 1) * S_WCH);
            uint32_t dst = swb + (buf ^ 1) * (S_WCH * 8);
#pragma unroll
            for (int it = 0; it < 3; it++)
                cp16(dst + (uint32_t)(tx + it * 256) * 16, src + (tx + it * 256) * 16);
            CP_COMMIT();
        }
        float xa[4][4];
#pragma unroll
        for (int r = 0; r < 4; r++) {
            float4 v4 = *(const float4*)(px[r] + c * 4);
            xa[r][0] = v4.x; xa[r][1] = v4.y; xa[r][2] = v4.z; xa[r][3] = v4.w;
        }
        const uint2* cw = SW[buf];
#pragma unroll
        for (int s = 0; s < 4; s++) {
            uint2 b[6];
#pragma unroll
            for (int j = 0; j < 6; j++)
                b[j] = cw[(s * 12 + wn * 6 + j) * 32 + lane];
            uint32_t fr[4];
            fr[0] = h2(xa[0][s] * eb2[0][1], xa[0][s] * eb2[0][0]);
            fr[1] = h2(xa[1][s] * eb2[1][1], xa[1][s] * eb2[1][0]);
            fr[2] = h2(xa[0][s] * eb2[0][3], xa[0][s] * eb2[0][2]);
            fr[3] = h2(xa[1][s] * eb2[1][3], xa[1][s] * eb2[1][2]);
#pragma unroll
            for (int j = 0; j < 6; j++) mma16(acc[0][j], fr, (const uint32_t*)&b[j]);
            fr[0] = h2(xa[2][s] * eb2[2][1], xa[2][s] * eb2[2][0]);
            fr[1] = h2(xa[3][s] * eb2[3][1], xa[3][s] * eb2[3][0]);
            fr[2] = h2(xa[2][s] * eb2[2][3], xa[2][s] * eb2[2][2]);
            fr[3] = h2(xa[3][s] * eb2[3][3], xa[3][s] * eb2[3][2]);
#pragma unroll
            for (int j = 0; j < 6; j++) mma16(acc[1][j], fr, (const uint32_t*)&b[j]);
        }
        CP_WAIT0();
        __syncthreads();
    }

    // ---- vv chunks 16..19: A[e,k'] = dot(v1[k'>>3], v2[k'&7]) / sqrt(3)
    // per step: lo k-group uses va=2s, hi uses va=2s+1; vb = {2t, 2t+1}
    float v2n[4][2][3];
#pragma unroll
    for (int r = 0; r < 4; r++)
#pragma unroll
        for (int d = 0; d < 2; d++)
#pragma unroll
            for (int m = 0; m < 3; m++) v2n[r][d][m] = pa[r][16 + (2 * t + d) * 3 + m];

#define DOT3(P, Q) (((P)[0] * (Q)[0] + (P)[1] * (Q)[1] + (P)[2] * (Q)[2]) * RSQRT3)

    for (int c = 16; c < 20; c++) {
        const int buf = c & 1;
        if (c < 19) {
            const char* src = (const char*)(g_wsh + (size_t)(c + 1) * S_WCH);
            uint32_t dst = swb + (buf ^ 1) * (S_WCH * 8);
#pragma unroll
            for (int it = 0; it < 3; it++)
                cp16(dst + (uint32_t)(tx + it * 256) * 16, src + (tx + it * 256) * 16);
            CP_COMMIT();
        }
        const uint2* cw = SW[buf];
        const int vab = (c - 16) * 8;
#pragma unroll
        for (int mt = 0; mt < 2; mt++) {
            const int r0 = 2 * mt, r1 = r0 + 1;
#pragma unroll
            for (int ks = 0; ks < 2; ks++) {
                float v1b[2][12];
#pragma unroll
                for (int r2 = 0; r2 < 2; r2++) {
                    const float* p = px[r0 + r2] + 64 + (vab + ks * 4) * 3;
                    float4 q0 = ((const float4*)p)[0];
                    float4 q1 = ((const float4*)p)[1];
                    float4 q2 = ((const float4*)p)[2];
                    v1b[r2][0] = q0.x; v1b[r2][1] = q0.y; v1b[r2][2]  = q0.z; v1b[r2][3]  = q0.w;
                    v1b[r2][4] = q1.x; v1b[r2][5] = q1.y; v1b[r2][6]  = q1.z; v1b[r2][7]  = q1.w;
                    v1b[r2][8] = q2.x; v1b[r2][9] = q2.y; v1b[r2][10] = q2.z; v1b[r2][11] = q2.w;
                }
#pragma unroll
                for (int ss = 0; ss < 2; ss++) {
                    const int s = ks * 2 + ss;
                    uint2 b[6];
#pragma unroll
                    for (int j = 0; j < 6; j++)
                        b[j] = cw[(s * 12 + wn * 6 + j) * 32 + lane];
                    const float* A00 = &v1b[0][(2 * ss) * 3];
                    const float* A01 = &v1b[0][(2 * ss + 1) * 3];
                    const float* A10 = &v1b[1][(2 * ss) * 3];
                    const float* A11 = &v1b[1][(2 * ss + 1) * 3];
                    uint32_t fr[4];
                    fr[0] = h2(DOT3(A00, v2n[r0][1]), DOT3(A00, v2n[r0][0]));
                    fr[1] = h2(DOT3(A10, v2n[r1][1]), DOT3(A10, v2n[r1][0]));
                    fr[2] = h2(DOT3(A01, v2n[r0][1]), DOT3(A01, v2n[r0][0]));
                    fr[3] = h2(DOT3(A11, v2n[r1][1]), DOT3(A11, v2n[r1][0]));
#pragma unroll
                    for (int j = 0; j < 6; j++) mma16(acc[mt][j], fr, (const uint32_t*)&b[j]);
                }
            }
        }
        if (c < 19) CP_WAIT0();
        __syncthreads();
    }

    // ---- epilogue
#pragma unroll
    for (int i = 0; i < 2; i++) {
#pragma unroll
        for (int j = 0; j < 6; j++) {
            int cb = (wn * 6 + j) * 8 + t * 2;
#pragma unroll
            for (int q = 0; q < 4; q++) {
                int r = i * 2 + ((q >= 2) ? 1 : 0);
                int cch = cb + (q & 1);
                float v = acc[i][j][q] * INVF;
                float sg = 1.f / (1.f + __expf(-v));
                if (cch < 64) atomicAdd(&g_sn[(size_t)node[r] * 64 + cch], v * sg);
                else          g_gate[(size_t)(e_base + el[r]) * 32 + (cch - 64)] = sg;
            }
        }
    }
}

// ------------------------- v-path kernel: 128 edges/CTA, fp16 mma, W via LDG -------------------------
__global__ void __launch_bounds__(256, 2) v_kernel(
    const float* __restrict__ x, const float* __restrict__ ea)
{
    const int tx = threadIdx.x, wid = tx >> 5, lane = tx & 31;
    const int g = lane >> 2, t = lane & 3;
    const int wm = wid & 3, wn = wid >> 2;
    const int e_base = blockIdx.x * 128;

    int el[4], node[4];
    const float *px[4], *pa[4];
    el[0] = wm * 16 + g; el[1] = el[0] + 8; el[2] = el[0] + 64; el[3] = el[1] + 64;
#pragma unroll
    for (int r = 0; r < 4; r++) {
        int e = e_base + el[r];
        node[r] = g_eidx[e];
        px[r] = x + (size_t)node[r] * 160;
        pa[r] = ea + (size_t)e * 40;
    }

    // b index: [((c*4+s)*4 + wn*2 + j)*32 + lane]
    const uint2* wb = g_wvh + (size_t)(wn * 2) * 32 + lane;

    float acc[2][3][2][4];
#pragma unroll
    for (int i = 0; i < 2; i++)
#pragma unroll
        for (int m = 0; m < 3; m++)
#pragma unroll
            for (int j = 0; j < 2; j++)
#pragma unroll
                for (int q = 0; q < 4; q++) acc[i][m][j][q] = 0.f;

    float v2n[4][2][3];
#pragma unroll
    for (int r = 0; r < 4; r++)
#pragma unroll
        for (int d = 0; d < 2; d++)
#pragma unroll
            for (int m = 0; m < 3; m++) v2n[r][d][m] = pa[r][16 + (2 * t + d) * 3 + m];

#define V_MMA(B0, B1, HALF, FR) do {                                                  \
    _Pragma("unroll")                                                                 \
    for (int m = 0; m < 3; m++) {                                                     \
        mma16(acc[HALF][m][0], (FR)[m], (const uint32_t*)&(B0));                      \
        mma16(acc[HALF][m][1], (FR)[m], (const uint32_t*)&(B1));                      \
    }                                                                                 \
} while (0)

    // ---- region A: A_m[e,k] = s1[k>>3] * v2[k&7][m], chunks 0..7
    // per step: lo k-group a0, hi a1; vb = {2t, 2t+1}
    for (int c = 0; c < 8; c++) {
        const uint2* wc = wb + (size_t)(c * 4) * 4 * 32;
#pragma unroll
        for (int half = 0; half < 2; half++) {
            const int r0 = half * 2, r1 = r0 + 1;
#pragma unroll
            for (int ks = 0; ks < 2; ks++) {
                float s1v[2][4];
#pragma unroll
                for (int r2 = 0; r2 < 2; r2++) {
                    float4 v4 = *(const float4*)(px[r0 + r2] + c * 8 + ks * 4);
                    s1v[r2][0] = v4.x; s1v[r2][1] = v4.y; s1v[r2][2] = v4.z; s1v[r2][3] = v4.w;
                }
#pragma unroll
                for (int ss = 0; ss < 2; ss++) {
                    const int s = ks * 2 + ss;
                    const int a0 = 2 * ss, a1 = 2 * ss + 1;
                    uint2 b0 = __ldg(wc + (size_t)(s * 4 + 0) * 32);
                    uint2 b1 = __ldg(wc + (size_t)(s * 4 + 1) * 32);
                    uint32_t fr[3][4];
#pragma unroll
                    for (int m = 0; m < 3; m++) {
                        fr[m][0] = h2(s1v[0][a0] * v2n[r0][1][m], s1v[0][a0] * v2n[r0][0][m]);
                        fr[m][1] = h2(s1v[1][a0] * v2n[r1][1][m], s1v[1][a0] * v2n[r1][0][m]);
                        fr[m][2] = h2(s1v[0][a1] * v2n[r0][1][m], s1v[0][a1] * v2n[r0][0][m]);
                        fr[m][3] = h2(s1v[1][a1] * v2n[r1][1][m], s1v[1][a1] * v2n[r1][0][m]);
                    }
                    V_MMA(b0, b1, half, fr);
                }
            }
        }
    }

    // ---- region B: A_m[e,k] = v1[k'>>4][m] * s2[k'&15], chunks 8..15 (one va per step)
    {
        float s2n[4][4];
#pragma unroll
        for (int r = 0; r < 4; r++) {
            s2n[r][0] = pa[r][2 * t];     s2n[r][1] = pa[r][2 * t + 1];
            s2n[r][2] = pa[r][2 * t + 8]; s2n[r][3] = pa[r][2 * t + 9];
        }
        for (int c = 8; c < 16; c++) {
            const uint2* wc = wb + (size_t)(c * 4) * 4 * 32;
#pragma unroll
            for (int half = 0; half < 2; half++) {
                const int r0 = half * 2, r1 = r0 + 1;
                float v1b[2][12];
#pragma unroll
                for (int r2 = 0; r2 < 2; r2++) {
                    const float* p = px[r0 + r2] + 64 + (c - 8) * 12;
                    float4 q0 = ((const float4*)p)[0];
                    float4 q1 = ((const float4*)p)[1];
                    float4 q2 = ((const float4*)p)[2];
                    v1b[r2][0] = q0.x; v1b[r2][1] = q0.y; v1b[r2][2]  = q0.z; v1b[r2][3]  = q0.w;
                    v1b[r2][4] = q1.x; v1b[r2][5] = q1.y; v1b[r2][6]  = q1.z; v1b[r2][7]  = q1.w;
                    v1b[r2][8] = q2.x; v1b[r2][9] = q2.y; v1b[r2][10] = q2.z; v1b[r2][11] = q2.w;
                }
#pragma unroll
                for (int s = 0; s < 4; s++) {
                    uint2 b0 = __ldg(wc + (size_t)(s * 4 + 0) * 32);
                    uint2 b1 = __ldg(wc + (size_t)(s * 4 + 1) * 32);
                    uint32_t fr[3][4];
#pragma unroll
                    for (int m = 0; m < 3; m++) {
                        float v0 = v1b[0][s * 3 + m], v1r = v1b[1][s * 3 + m];
                        fr[m][0] = h2(v0 * s2n[r0][1],  v0 * s2n[r0][0]);
                        fr[m][1] = h2(v1r * s2n[r1][1], v1r * s2n[r1][0]);
                        fr[m][2] = h2(v0 * s2n[r0][3],  v0 * s2n[r0][2]);
                        fr[m][3] = h2(v1r * s2n[r1][3], v1r * s2n[r1][2]);
                    }
                    V_MMA(b0, b1, half, fr);
                }
            }
        }
    }

    // ---- region C: cross(v1, v2)[m]/sqrt(2), chunks 16..19
#define CRX(P, Q) (((P)[m1] * (Q)[m2] - (P)[m2] * (Q)[m1]) * RSQRT2)
    for (int c = 16; c < 20; c++) {
        const uint2* wc = wb + (size_t)(c * 4) * 4 * 32;
        const int vab = (c - 16) * 8;
#pragma unroll
        for (int half = 0; half < 2; half++) {
            const int r0 = half * 2, r1 = r0 + 1;
#pragma unroll
            for (int ks = 0; ks < 2; ks++) {
                float v1b[2][12];
#pragma unroll
                for (int r2 = 0; r2 < 2; r2++) {
                    const float* p = px[r0 + r2] + 64 + (vab + ks * 4) * 3;
                    float4 q0 = ((const float4*)p)[0];
                    float4 q1 = ((const float4*)p)[1];
                    float4 q2 = ((const float4*)p)[2];
                    v1b[r2][0] = q0.x; v1b[r2][1] = q0.y; v1b[r2][2]  = q0.z; v1b[r2][3]  = q0.w;
                    v1b[r2][4] = q1.x; v1b[r2][5] = q1.y; v1b[r2][6]  = q1.z; v1b[r2][7]  = q1.w;
                    v1b[r2][8] = q2.x; v1b[r2][9] = q2.y; v1b[r2][10] = q2.z; v1b[r2][11] = q2.w;
                }
#pragma unroll
                for (int ss = 0; ss < 2; ss++) {
                    const int s = ks * 2 + ss;
                    uint2 b0 = __ldg(wc + (size_t)(s * 4 + 0) * 32);
                    uint2 b1 = __ldg(wc + (size_t)(s * 4 + 1) * 32);
                    const float* A00 = &v1b[0][(2 * ss) * 3];
                    const float* A01 = &v1b[0][(2 * ss + 1) * 3];
                    const float* A10 = &v1b[1][(2 * ss) * 3];
                    const float* A11 = &v1b[1][(2 * ss + 1) * 3];
                    uint32_t fr[3][4];
#pragma unroll
                    for (int m = 0; m < 3; m++) {
                        const int m1 = (m == 2) ? 0 : m + 1;
                        const int m2 = (m == 0) ? 2 : m - 1;
                        fr[m][0] = h2(CRX(A00, v2n[r0][1]), CRX(A00, v2n[r0][0]));
                        fr[m][1] = h2(CRX(A10, v2n[r1][1]), CRX(A10, v2n[r1][0]));
                        fr[m][2] = h2(CRX(A01, v2n[r0][1]), CRX(A01, v2n[r0][0]));
                        fr[m][3] = h2(CRX(A11, v2n[r1][1]), CRX(A11, v2n[r1][0]));
                    }
                    V_MMA(b0, b1, half, fr);
                }
            }
        }
    }

    // ---- epilogue: gate & scatter
#pragma unroll
    for (int i = 0; i < 2; i++) {
#pragma unroll
        for (int j = 0; j < 2; j++) {
            int cb = (wn * 2 + j) * 8 + t * 2;
#pragma unroll
            for (int q = 0; q < 4; q++) {
                int r = i * 2 + ((q >= 2) ? 1 : 0);
                int cch = cb + (q & 1);
                float gt = g_gate[(size_t)(e_base + el[r]) * 32 + cch] * INVF;
#pragma unroll
                for (int m = 0; m < 3; m++)
                    atomicAdd(&g_vn[(size_t)node[r] * 96 + cch * 3 + m], acc[i][m][j][q] * gt);
            }
        }
    }
}

// ------------------------- BN stats -------------------------
__global__ void stats_kernel() {
    __shared__ double red[256];
    __shared__ double red2[256];
    int c = blockIdx.x;
    int tx = threadIdx.x;
    double s = 0.0, s2 = 0.0;
    if (c < 64) {
        for (int n = tx; n < NN; n += 256) {
            float v = g_sn[(size_t)n * 64 + c];
            s += (double)v; s2 += (double)v * (double)v;
        }
    } else {
        int cv = c - 64;
        for (int n = tx; n < NN; n += 256) {
            const float* p = &g_vn[(size_t)n * 96 + cv * 3];
            s += (double)p[0] * p[0] + (double)p[1] * p[1] + (double)p[2] * p[2];
        }
    }
    red[tx] = s; red2[tx] = s2;
    __syncthreads();
    for (int o = 128; o > 0; o >>= 1) {
        if (tx < o) { red[tx] += red[tx + o]; red2[tx] += red2[tx + o]; }
        __syncthreads();
    }
    if (tx == 0) {
        if (c < 64) {
            double mu = red[0] / (double)NN;
            g_mu[c] = (float)mu;
            g_var[c] = (float)(red2[0] / (double)NN - mu * mu);
        } else {
            g_vnorm[c - 64] = (float)(red[0] / ((double)NN * 3.0));
        }
    }
}

// ------------------------- finalize -------------------------
__global__ void finalize_kernel(
    const float* __restrict__ x,
    const float* __restrict__ bn_w_s, const float* __restrict__ bn_b_s,
    const float* __restrict__ bn_w_v, float* __restrict__ out)
{
    int idx = blockIdx.x * 256 + threadIdx.x;
    if (idx >= NN * 160) return;
    int n = idx / 160, j = idx % 160;
    float xv = x[idx];
    float r;
    if (j < 64) {
        float v = g_sn[(size_t)n * 64 + j];
        r = (v - g_mu[j]) * rsqrtf(g_var[j] + 1e-5f) * bn_w_s[j] + bn_b_s[j];
    } else {
        int jj = j - 64;
        int a = jj / 3;
        r = g_vn[(size_t)n * 96 + jj] * rsqrtf(g_vnorm[a] + 1e-5f) * bn_w_v[a];
    }
    out[idx] = r + xv;
}

// ------------------------- launcher -------------------------
extern "C" void kernel_launch(void* const* d_in, const int* in_sizes, int n_in,
                              void* d_out, int out_size)
{
    const float* x      = (const float*)d_in[0];
    const float* ea     = (const float*)d_in[1];
    const float* W_ss   = (const float*)d_in[2];
    const float* W_vv_s = (const float*)d_in[3];
    const float* W_sv   = (const float*)d_in[4];
    const float* W_vs   = (const float*)d_in[5];
    const float* W_vv_v = (const float*)d_in[6];
    const float* bnws   = (const float*)d_in[7];
    const float* bnbs   = (const float*)d_in[8];
    const float* bnwv   = (const float*)d_in[9];
    const void*  eidx   = d_in[10];
    float* out = (float*)d_out;

    // launch index 2 == s_kernel, 3 == v_kernel
    detect_kernel<<<1, 256>>>((const long long*)eidx);
    mega_prep<<<6410, 256>>>(eidx, W_ss, W_vv_s, W_sv, W_vs, W_vv_v);
    s_kernel<<<NE / 128, 256>>>(x, ea);
    v_kernel<<<NE / 128, 256>>>(x, ea);
    stats_kernel<<<96, 256>>>();
    finalize_kernel<<<(NN * 160 + 255) / 256, 256>>>(x, bnws, bnbs, bnwv, out);
}